// round 1
// baseline (speedup 1.0000x reference)
#include <cuda_runtime.h>
#include <math_constants.h>

// RightPool: out[b,c,h,w] = max(x[b,c,h,0..w])  — inclusive cummax along last
// axis, W = 128, fp32. Tensor (8,256,128,128) -> 262,144 rows of 128 floats.
//
// Strategy: one warp per row. Lane l owns elements [4l, 4l+4) via one float4
// load (coalesced 512B/warp). Sequential prefix-max in registers, then a
// 5-step shfl_up inclusive max-scan across lanes to get each lane's exclusive
// prefix, then combine and store one float4.

static constexpr int W = 128;          // row length (elements)
static constexpr int WARPS_PER_BLOCK = 8;
static constexpr int THREADS = WARPS_PER_BLOCK * 32;

__global__ __launch_bounds__(THREADS)
void rightpool_kernel(const float* __restrict__ x,
                      float* __restrict__ out,
                      int num_rows) {
    const int warp_in_block = threadIdx.x >> 5;
    const int lane          = threadIdx.x & 31;
    const int row           = blockIdx.x * WARPS_PER_BLOCK + warp_in_block;
    if (row >= num_rows) return;

    const size_t base = (size_t)row * W + (size_t)lane * 4;

    // Coalesced 16B load per lane.
    float4 v = *reinterpret_cast<const float4*>(x + base);

    // Local inclusive prefix max over the 4 elements.
    float p0 = v.x;
    float p1 = fmaxf(p0, v.y);
    float p2 = fmaxf(p1, v.z);
    float p3 = fmaxf(p2, v.w);

    // Inclusive max-scan of lane totals (p3) across the warp.
    float scan = p3;
    #pragma unroll
    for (int ofs = 1; ofs < 32; ofs <<= 1) {
        float n = __shfl_up_sync(0xFFFFFFFFu, scan, ofs);
        if (lane >= ofs) scan = fmaxf(scan, n);
    }

    // Exclusive prefix for this lane = inclusive scan of lane-1.
    float excl = __shfl_up_sync(0xFFFFFFFFu, scan, 1);
    if (lane == 0) excl = -CUDART_INF_F;

    float4 o;
    o.x = fmaxf(excl, p0);
    o.y = fmaxf(excl, p1);
    o.z = fmaxf(excl, p2);
    o.w = fmaxf(excl, p3);

    *reinterpret_cast<float4*>(out + base) = o;
}

extern "C" void kernel_launch(void* const* d_in, const int* in_sizes, int n_in,
                              void* d_out, int out_size) {
    const float* x = (const float*)d_in[0];
    float* out = (float*)d_out;
    const int n = in_sizes[0];
    const int num_rows = n / W;

    const int blocks = (num_rows + WARPS_PER_BLOCK - 1) / WARPS_PER_BLOCK;
    rightpool_kernel<<<blocks, THREADS>>>(x, out, num_rows);
}

// round 2
// speedup vs baseline: 1.0366x; 1.0366x over previous
#include <cuda_runtime.h>
#include <math_constants.h>

// RightPool: out[b,c,h,w] = max(x[b,c,h,0..w]) — inclusive cummax along last
// axis, W = 128, fp32. Tensor (8,256,128,128) -> 262,144 rows of 128 floats.
//
// R1 -> R2 change: 4 rows per warp (independent scan chains interleaved) to
// raise per-warp MLP from 1 to 4 and pipeline the SHFL-chain latency.
// Scan predicates removed (shfl_up is idempotent under fmax for lane < ofs).

static constexpr int W = 128;           // row length (elements)
static constexpr int R = 4;             // rows per warp
static constexpr int WARPS_PER_BLOCK = 8;
static constexpr int THREADS = WARPS_PER_BLOCK * 32;
static constexpr int ROWS_PER_BLOCK = WARPS_PER_BLOCK * R;

__global__ __launch_bounds__(THREADS)
void rightpool_kernel(const float* __restrict__ x,
                      float* __restrict__ out,
                      int num_rows) {
    const int warp_in_block = threadIdx.x >> 5;
    const int lane          = threadIdx.x & 31;
    const int row0 = (blockIdx.x * WARPS_PER_BLOCK + warp_in_block) * R;

    // Grid is sized so full blocks always fit (num_rows % ROWS_PER_BLOCK == 0
    // for this shape), but guard anyway.
    if (row0 + R > num_rows) {
        for (int r = 0; r < R; r++) {
            int row = row0 + r;
            if (row >= num_rows) return;
            const size_t base = (size_t)row * W + (size_t)lane * 4;
            float4 v = *reinterpret_cast<const float4*>(x + base);
            float p0 = v.x, p1 = fmaxf(p0, v.y), p2 = fmaxf(p1, v.z), p3 = fmaxf(p2, v.w);
            float s = p3;
            #pragma unroll
            for (int ofs = 1; ofs < 32; ofs <<= 1)
                s = fmaxf(s, __shfl_up_sync(0xFFFFFFFFu, s, ofs));
            float e = __shfl_up_sync(0xFFFFFFFFu, s, 1);
            if (lane == 0) e = -CUDART_INF_F;
            float4 o = {fmaxf(e, p0), fmaxf(e, p1), fmaxf(e, p2), fmaxf(e, p3)};
            *reinterpret_cast<float4*>(out + base) = o;
        }
        return;
    }

    // ---- Fast path: 4 independent rows, fully interleaved ----
    float4 v[R];
    #pragma unroll
    for (int r = 0; r < R; r++) {
        const size_t base = (size_t)(row0 + r) * W + (size_t)lane * 4;
        v[r] = *reinterpret_cast<const float4*>(x + base);
    }

    // Local inclusive prefix max (per row).
    float p0[R], p1[R], p2[R], p3[R];
    #pragma unroll
    for (int r = 0; r < R; r++) {
        p0[r] = v[r].x;
        p1[r] = fmaxf(p0[r], v[r].y);
        p2[r] = fmaxf(p1[r], v[r].z);
        p3[r] = fmaxf(p2[r], v[r].w);
    }

    // Interleaved inclusive max-scans across lanes. shfl_up returns the
    // caller's own value when lane < ofs, and fmax(s,s)=s, so no predicate.
    float s[R];
    #pragma unroll
    for (int r = 0; r < R; r++) s[r] = p3[r];

    #pragma unroll
    for (int ofs = 1; ofs < 32; ofs <<= 1) {
        float n[R];
        #pragma unroll
        for (int r = 0; r < R; r++) n[r] = __shfl_up_sync(0xFFFFFFFFu, s[r], ofs);
        #pragma unroll
        for (int r = 0; r < R; r++) s[r] = fmaxf(s[r], n[r]);
    }

    // Exclusive prefix per lane.
    float e[R];
    #pragma unroll
    for (int r = 0; r < R; r++) {
        e[r] = __shfl_up_sync(0xFFFFFFFFu, s[r], 1);
        if (lane == 0) e[r] = -CUDART_INF_F;
    }

    #pragma unroll
    for (int r = 0; r < R; r++) {
        const size_t base = (size_t)(row0 + r) * W + (size_t)lane * 4;
        float4 o;
        o.x = fmaxf(e[r], p0[r]);
        o.y = fmaxf(e[r], p1[r]);
        o.z = fmaxf(e[r], p2[r]);
        o.w = fmaxf(e[r], p3[r]);
        *reinterpret_cast<float4*>(out + base) = o;
    }
}

extern "C" void kernel_launch(void* const* d_in, const int* in_sizes, int n_in,
                              void* d_out, int out_size) {
    const float* x = (const float*)d_in[0];
    float* out = (float*)d_out;
    const int n = in_sizes[0];
    const int num_rows = n / W;

    const int blocks = (num_rows + ROWS_PER_BLOCK - 1) / ROWS_PER_BLOCK;
    rightpool_kernel<<<blocks, THREADS>>>(x, out, num_rows);
}

// round 3
// speedup vs baseline: 1.0440x; 1.0071x over previous
#include <cuda_runtime.h>
#include <math_constants.h>

// RightPool: out[b,c,h,w] = max(x[b,c,h,0..w]) — inclusive cummax along last
// axis, W = 128, fp32. Tensor (8,256,128,128) -> 262,144 rows of 128 floats.
//
// R2 -> R3: 8 rows per warp (front-batched LDG.128 x8 for MLP_p1=8),
// in-place prefix to cap live registers, streaming cache hints
// (__ldcs / __stcs) since there is zero data reuse.

static constexpr int W = 128;           // row length (elements)
static constexpr int R = 8;             // rows per warp
static constexpr int WARPS_PER_BLOCK = 8;
static constexpr int THREADS = WARPS_PER_BLOCK * 32;
static constexpr int ROWS_PER_BLOCK = WARPS_PER_BLOCK * R;

__device__ __forceinline__ float4 ldcs4(const float* p) {
    return __ldcs(reinterpret_cast<const float4*>(p));
}
__device__ __forceinline__ void stcs4(float* p, float4 v) {
    __stcs(reinterpret_cast<float4*>(p), v);
}

__global__ __launch_bounds__(THREADS)
void rightpool_kernel(const float* __restrict__ x,
                      float* __restrict__ out,
                      int num_rows) {
    const int warp_in_block = threadIdx.x >> 5;
    const int lane          = threadIdx.x & 31;
    const int row0 = (blockIdx.x * WARPS_PER_BLOCK + warp_in_block) * R;

    // Tail path (not taken for this shape: 262144 % 64 == 0).
    if (row0 + R > num_rows) {
        for (int r = 0; r < R; r++) {
            int row = row0 + r;
            if (row >= num_rows) return;
            const size_t base = (size_t)row * W + (size_t)lane * 4;
            float4 v = ldcs4(x + base);
            v.y = fmaxf(v.x, v.y); v.z = fmaxf(v.y, v.z); v.w = fmaxf(v.z, v.w);
            float s = v.w;
            #pragma unroll
            for (int ofs = 1; ofs < 32; ofs <<= 1)
                s = fmaxf(s, __shfl_up_sync(0xFFFFFFFFu, s, ofs));
            float e = __shfl_up_sync(0xFFFFFFFFu, s, 1);
            if (lane == 0) e = -CUDART_INF_F;
            float4 o = {fmaxf(e, v.x), fmaxf(e, v.y), fmaxf(e, v.z), fmaxf(e, v.w)};
            stcs4(out + base, o);
        }
        return;
    }

    const size_t base0 = (size_t)row0 * W + (size_t)lane * 4;

    // ---- Front-batched loads: 8 independent LDG.128 (MLP_p1 = 8) ----
    float4 v[R];
    #pragma unroll
    for (int r = 0; r < R; r++)
        v[r] = ldcs4(x + base0 + (size_t)r * W);

    // In-place local inclusive prefix max (per row).
    #pragma unroll
    for (int r = 0; r < R; r++) {
        v[r].y = fmaxf(v[r].x, v[r].y);
        v[r].z = fmaxf(v[r].y, v[r].z);
        v[r].w = fmaxf(v[r].z, v[r].w);
    }

    // Interleaved inclusive max-scans of the lane totals across lanes.
    // shfl_up returns the caller's own value when lane < ofs, and
    // fmax(s,s)=s, so no predicate needed.
    float s[R];
    #pragma unroll
    for (int r = 0; r < R; r++) s[r] = v[r].w;

    #pragma unroll
    for (int ofs = 1; ofs < 32; ofs <<= 1) {
        float n[R];
        #pragma unroll
        for (int r = 0; r < R; r++) n[r] = __shfl_up_sync(0xFFFFFFFFu, s[r], ofs);
        #pragma unroll
        for (int r = 0; r < R; r++) s[r] = fmaxf(s[r], n[r]);
    }

    // Exclusive prefix per lane, combine, store.
    #pragma unroll
    for (int r = 0; r < R; r++) {
        float e = __shfl_up_sync(0xFFFFFFFFu, s[r], 1);
        if (lane == 0) e = -CUDART_INF_F;
        float4 o;
        o.x = fmaxf(e, v[r].x);
        o.y = fmaxf(e, v[r].y);
        o.z = fmaxf(e, v[r].z);
        o.w = fmaxf(e, v[r].w);
        stcs4(out + base0 + (size_t)r * W, o);
    }
}

extern "C" void kernel_launch(void* const* d_in, const int* in_sizes, int n_in,
                              void* d_out, int out_size) {
    const float* x = (const float*)d_in[0];
    float* out = (float*)d_out;
    const int n = in_sizes[0];
    const int num_rows = n / W;

    const int blocks = (num_rows + ROWS_PER_BLOCK - 1) / ROWS_PER_BLOCK;
    rightpool_kernel<<<blocks, THREADS>>>(x, out, num_rows);
}